// round 5
// baseline (speedup 1.0000x reference)
#include <cuda_runtime.h>
#include <cuda_fp16.h>

// Fused curve-LUT apply (trilinear grid_sample over 8x256x256 control grid + tanh).
//
// R5 = R4 (fp16 overlapping-pair shared layout, 32x32 tile, 30KB smem) with the
// 4-corner bilinear blend done in PACKED FP16 (HMUL2/HFMA2) on the (a,b)
// endpoint pairs, pairwise (2 corners per fp16 chain) to bound rounding error,
// converting to fp32 only twice per (i,channel) instead of four times.
//   F2F/pixel: 72 -> ~40,  FFMA/pixel: 72 -> ~45, +36 HFMA2-class ops.
// The R4 profile showed issue=69%/alu=58% as the limiter with L1 at 44%;
// this cuts issued instructions ~30% without touching LDS count or occupancy.

#define TW 32
#define TH 32
#define XS 10
#define YS 10
#define NP (XS * YS)       // 100 points
#define PSTR 25            // half2 per point (24 used: 3ch * 8 pairs), odd stride
#define ISTR (NP * PSTR)   // half2 per curve set
#define NTHREADS 256

__device__ __forceinline__ float fast_tanh(float v) {
    float y;
    asm("tanh.approx.f32 %0, %1;" : "=f"(y) : "f"(v));
    return y;
}

__global__ __launch_bounds__(NTHREADS)
void curve_apply_kernel(const float* __restrict__ x,
                        const float* __restrict__ param,
                        float* __restrict__ out)
{
    __shared__ __half2 sh[3 * ISTR];   // 7500 half2 = 30,000 B

    const int b  = blockIdx.z;
    const int w0 = blockIdx.x * TW;
    const int h0 = blockIdx.y * TH;
    const float r = 255.0f / 1023.0f;
    const int xbase = (int)floorf((float)w0 * r);
    const int ybase = (int)floorf((float)h0 * r);
    const int tid = threadIdx.x;

    // ---- Stage control patch -> fp16 overlapping pairs ----
    // plane = c*24 + i*8 + z.  v[z] -> pair[z].x and pair[z-1].y; z==7 also pair[7].y.
    const float* prm = param + (size_t)b * 72 * 65536;
    #pragma unroll 1
    for (int idx = tid; idx < 72 * NP; idx += NTHREADS) {
        int plane = idx / NP;
        int pos   = idx - plane * NP;
        int dy = pos / XS;
        int dx = pos - dy * XS;
        int yy = min(ybase + dy, 255);
        int xx = min(xbase + dx, 255);
        float v = __ldg(prm + plane * 65536 + yy * 256 + xx);
        int c  = plane / 24;
        int rm = plane - c * 24;
        int i  = rm >> 3;
        int z  = rm & 7;
        __half hv = __float2half_rn(v);
        __half* hb = (__half*)(sh + (i * NP + pos) * PSTR) + c * 16;
        hb[2 * z] = hv;                  // pair[z].x
        if (z > 0)  hb[2 * z - 1] = hv;  // pair[z-1].y
        if (z == 7) hb[15] = hv;         // pair[7].y (depth clamp)
    }
    __syncthreads();

    // ---- Pixel loop ----
    const int lane = tid & 31;
    const int rowi = tid >> 5;
    const int w = w0 + lane;

    float ixf = fminf((float)w * r, 255.0f);
    float x0f = floorf(ixf);
    float wx  = ixf - x0f;
    int   x0  = (int)x0f;
    int   dx0 = x0 - xbase;
    int   dx1 = min(x0 + 1, 255) - xbase;

    const float* xb = x   + (size_t)b * 3 * 1048576;
    float*       ob = out + (size_t)b * 3 * 1048576;

    #pragma unroll
    for (int k = 0; k < 4; k++) {
        int h = h0 + rowi + 8 * k;
        float iyf = fminf((float)h * r, 255.0f);
        float y0f = floorf(iyf);
        float wy  = iyf - y0f;
        int   y0  = (int)y0f;
        int   dy0 = y0 - ybase;
        int   dy1 = min(y0 + 1, 255) - ybase;

        int cb00 = (dy0 * XS + dx0) * PSTR;
        int cb01 = (dy0 * XS + dx1) * PSTR;
        int cb10 = (dy1 * XS + dx0) * PSTR;
        int cb11 = (dy1 * XS + dx1) * PSTR;

        float w11 = wy * wx;
        float w10 = wy - w11;
        float w01 = wx - w11;
        float w00 = 1.0f - wy - wx + w11;

        const __half2 hw00 = __half2half2(__float2half_rn(w00));
        const __half2 hw01 = __half2half2(__float2half_rn(w01));
        const __half2 hw10 = __half2half2(__float2half_rn(w10));
        const __half2 hw11 = __half2half2(__float2half_rn(w11));

        int pix = h * 1024 + w;
        float acc0 = 0.f, acc1 = 0.f, acc2 = 0.f;

        #pragma unroll
        for (int i = 0; i < 3; i++) {
            float gz  = __ldg(xb + (size_t)i * 1048576 + pix);
            float izf = fminf(fmaxf(fmaf(gz, 3.5f, 3.5f), 0.0f), 7.0f);
            float z0f = floorf(izf);
            float wz  = izf - z0f;
            int   z0  = (int)z0f;
            const __half2* shi = sh + i * ISTR + z0;
            const __half2* p00 = shi + cb00;
            const __half2* p01 = shi + cb01;
            const __half2* p10 = shi + cb10;
            const __half2* p11 = shi + cb11;

            #define CHAN(OFF, ACC)                                            \
            {                                                                 \
                __half2 t = __hfma2(hw01, p01[OFF], __hmul2(hw00, p00[OFF])); \
                __half2 u = __hfma2(hw11, p11[OFF], __hmul2(hw10, p10[OFF])); \
                float2 tf = __half22float2(t);                                \
                float2 uf = __half22float2(u);                                \
                float A = tf.x + uf.x;                                        \
                float B = tf.y + uf.y;                                        \
                ACC += fmaf(wz, B - A, A);                                    \
            }
            CHAN(0,  acc0)
            CHAN(8,  acc1)
            CHAN(16, acc2)
            #undef CHAN
        }

        ob[pix]           = fast_tanh(acc0);
        ob[1048576 + pix] = fast_tanh(acc1);
        ob[2097152 + pix] = fast_tanh(acc2);
    }
}

extern "C" void kernel_launch(void* const* d_in, const int* in_sizes, int n_in,
                              void* d_out, int out_size)
{
    const float* x     = (const float*)d_in[0];   // [4,3,1024,1024] fp32
    const float* param = (const float*)d_in[1];   // [4,72,256,256]  fp32
    float*       out   = (float*)d_out;           // [4,3,1024,1024] fp32

    dim3 grid(1024 / TW, 1024 / TH, 4);
    curve_apply_kernel<<<grid, NTHREADS>>>(x, param, out);
}

// round 6
// speedup vs baseline: 1.1267x; 1.1267x over previous
#include <cuda_runtime.h>
#include <cuda_fp16.h>

// Fused curve-LUT apply (trilinear grid_sample over 8x256x256 control grid + tanh).
//
// R6: latency-hiding round. R5 showed no pipe >65% (latency-bound), occ=68%
// (reg-limited, 6 CTAs x 8 warps). Change: 512 threads/CTA, 2 px/thread,
// __launch_bounds__(512,4) -> 4 CTAs x 16 warps = 64 warps = 100% theoretical
// occupancy (smem 30KB x 4 = 120KB fits). All 6 x-LDGs batched up-front for
// MLP. Shared layout and fp16 HFMA2 corner blend unchanged from R5
// (36 LDS.32 + 144B per pixel, fp32 z-lerp, rel_err ~3.6e-4 < 1e-3).

#define TW 32
#define TH 32
#define XS 10
#define YS 10
#define NP (XS * YS)       // 100 points
#define PSTR 25            // half2 per point (24 used: 3ch * 8 pairs), odd stride
#define ISTR (NP * PSTR)   // half2 per curve set
#define NTHREADS 512

__device__ __forceinline__ float fast_tanh(float v) {
    float y;
    asm("tanh.approx.f32 %0, %1;" : "=f"(y) : "f"(v));
    return y;
}

__global__ __launch_bounds__(NTHREADS, 4)
void curve_apply_kernel(const float* __restrict__ x,
                        const float* __restrict__ param,
                        float* __restrict__ out)
{
    __shared__ __half2 sh[3 * ISTR];   // 7500 half2 = 30,000 B

    const int b  = blockIdx.z;
    const int w0 = blockIdx.x * TW;
    const int h0 = blockIdx.y * TH;
    const float r = 255.0f / 1023.0f;
    const int xbase = (int)floorf((float)w0 * r);
    const int ybase = (int)floorf((float)h0 * r);
    const int tid = threadIdx.x;

    // ---- Stage control patch -> fp16 overlapping pairs ----
    // plane = c*24 + i*8 + z.  v[z] -> pair[z].x and pair[z-1].y; z==7 also pair[7].y.
    const float* prm = param + (size_t)b * 72 * 65536;
    #pragma unroll 1
    for (int idx = tid; idx < 72 * NP; idx += NTHREADS) {
        int plane = idx / NP;
        int pos   = idx - plane * NP;
        int dy = pos / XS;
        int dx = pos - dy * XS;
        int yy = min(ybase + dy, 255);
        int xx = min(xbase + dx, 255);
        float v = __ldg(prm + plane * 65536 + yy * 256 + xx);
        int c  = plane / 24;
        int rm = plane - c * 24;
        int i  = rm >> 3;
        int z  = rm & 7;
        __half hv = __float2half_rn(v);
        __half* hb = (__half*)(sh + (i * NP + pos) * PSTR) + c * 16;
        hb[2 * z] = hv;                  // pair[z].x
        if (z > 0)  hb[2 * z - 1] = hv;  // pair[z-1].y
        if (z == 7) hb[15] = hv;         // pair[7].y (depth clamp)
    }
    __syncthreads();

    // ---- Pixel loop: 16 warps, lane = x, each thread owns 2 rows ----
    const int lane = tid & 31;
    const int rowi = tid >> 5;          // 0..15
    const int w = w0 + lane;

    float ixf = fminf((float)w * r, 255.0f);
    float x0f = floorf(ixf);
    float wx  = ixf - x0f;
    int   x0  = (int)x0f;
    int   dx0 = x0 - xbase;
    int   dx1 = min(x0 + 1, 255) - xbase;

    const float* xb = x   + (size_t)b * 3 * 1048576;
    float*       ob = out + (size_t)b * 3 * 1048576;

    const int h_a = h0 + rowi;
    const int h_b = h_a + 16;
    const int pixA = h_a * 1024 + w;
    const int pixB = h_b * 1024 + w;

    // Batched x loads: 6 independent LDGs up-front (MLP).
    float gz_[2][3];
    gz_[0][0] = __ldg(xb + pixA);
    gz_[0][1] = __ldg(xb + 1048576 + pixA);
    gz_[0][2] = __ldg(xb + 2097152 + pixA);
    gz_[1][0] = __ldg(xb + pixB);
    gz_[1][1] = __ldg(xb + 1048576 + pixB);
    gz_[1][2] = __ldg(xb + 2097152 + pixB);

    #pragma unroll
    for (int k = 0; k < 2; k++) {
        const int h = (k == 0) ? h_a : h_b;
        const int pix = (k == 0) ? pixA : pixB;

        float iyf = fminf((float)h * r, 255.0f);
        float y0f = floorf(iyf);
        float wy  = iyf - y0f;
        int   y0  = (int)y0f;
        int   dy0 = y0 - ybase;
        int   dy1 = min(y0 + 1, 255) - ybase;

        int cb00 = (dy0 * XS + dx0) * PSTR;
        int cb01 = (dy0 * XS + dx1) * PSTR;
        int cb10 = (dy1 * XS + dx0) * PSTR;
        int cb11 = (dy1 * XS + dx1) * PSTR;

        float w11 = wy * wx;
        float w10 = wy - w11;
        float w01 = wx - w11;
        float w00 = 1.0f - wy - wx + w11;

        const __half2 hw00 = __half2half2(__float2half_rn(w00));
        const __half2 hw01 = __half2half2(__float2half_rn(w01));
        const __half2 hw10 = __half2half2(__float2half_rn(w10));
        const __half2 hw11 = __half2half2(__float2half_rn(w11));

        float acc0 = 0.f, acc1 = 0.f, acc2 = 0.f;

        #pragma unroll
        for (int i = 0; i < 3; i++) {
            float gz  = gz_[k][i];
            float izf = fminf(fmaxf(fmaf(gz, 3.5f, 3.5f), 0.0f), 7.0f);
            float z0f = floorf(izf);
            float wz  = izf - z0f;
            int   z0  = (int)z0f;
            const __half2* shi = sh + i * ISTR + z0;
            const __half2* p00 = shi + cb00;
            const __half2* p01 = shi + cb01;
            const __half2* p10 = shi + cb10;
            const __half2* p11 = shi + cb11;

            #define CHAN(OFF, ACC)                                            \
            {                                                                 \
                __half2 t = __hfma2(hw01, p01[OFF], __hmul2(hw00, p00[OFF])); \
                __half2 u = __hfma2(hw11, p11[OFF], __hmul2(hw10, p10[OFF])); \
                float2 tf = __half22float2(t);                                \
                float2 uf = __half22float2(u);                                \
                float A = tf.x + uf.x;                                        \
                float B = tf.y + uf.y;                                        \
                ACC += fmaf(wz, B - A, A);                                    \
            }
            CHAN(0,  acc0)
            CHAN(8,  acc1)
            CHAN(16, acc2)
            #undef CHAN
        }

        ob[pix]           = fast_tanh(acc0);
        ob[1048576 + pix] = fast_tanh(acc1);
        ob[2097152 + pix] = fast_tanh(acc2);
    }
}

extern "C" void kernel_launch(void* const* d_in, const int* in_sizes, int n_in,
                              void* d_out, int out_size)
{
    const float* x     = (const float*)d_in[0];   // [4,3,1024,1024] fp32
    const float* param = (const float*)d_in[1];   // [4,72,256,256]  fp32
    float*       out   = (float*)d_out;           // [4,3,1024,1024] fp32

    dim3 grid(1024 / TW, 1024 / TH, 4);
    curve_apply_kernel<<<grid, NTHREADS>>>(x, param, out);
}